// round 13
// baseline (speedup 1.0000x reference)
#include <cuda_runtime.h>
#include <math.h>
#include <stdint.h>

#define HID     256
#define NSTEPS  52
#define BATCH   1024

// ---------------- persistent state (device globals; no allocation) ----------
__device__ float g_hd[2][4][BATCH][HID];  // double-buffered h (tf32-rounded)
__device__ float g_c[4][BATCH][HID];      // full fp32 cell state
__device__ float g_y [BATCH][512];        // layer-0 input (prev y, tf32-rounded)
__device__ float g_x1[BATCH][512];        // layer-1 input (concat h, tf32-rounded)
__device__ float g_Wp[4][1024][768];      // packed weights [lz][j*4+gate][k], tf32
__device__ float g_bias[4][1024];         // bih+bhh, packed row order j*4+gate
__device__ unsigned g_bar[8][32];         // per-band barrier counters (128B apart)

// ---------------- helpers ---------------------------------------------------
__device__ __forceinline__ unsigned f2tf32(float x) {
    unsigned u;
    asm("cvt.rna.tf32.f32 %0, %1;" : "=r"(u) : "f"(x));
    return u;
}
__device__ __forceinline__ float tf32r(float x) { return __uint_as_float(f2tf32(x)); }

__device__ __forceinline__ uint32_t smem_u32(const void* p) {
    uint32_t a;
    asm("{ .reg .u64 t; cvta.to.shared.u64 t, %1; cvt.u32.u64 %0, t; }" : "=r"(a) : "l"(p));
    return a;
}
__device__ __forceinline__ float sigf(float x) { return 1.f / (1.f + __expf(-x)); }

#define NTHREADS 512
#define KHALF   384            // K split: warps 0-7 do K[0:384), 8-15 do K[384:768)
#define NITER   12             // 384 / 32 chunks per half
#define STAGEB  65536          // one stage: [A0 16K][B0 16K][A1 16K][B1 16K]
#define GSTRIDE 132            // epilogue gate smem row stride (floats), padded
#define GBUFB   67584          // 128 * GSTRIDE * 4 bytes per half-buffer

// ---------------- persistent fused LSTM kernel ------------------------------
// 128 CTAs (<=148 SMs -> co-resident). CTA bx: band=bx>>4 (batch rows band*128),
// sub=bx&15: n0=(sub>>1)*128 (gate-row tile), z=sub&1 (direction).
// 16 warps: kh=warp>>3 selects K-half; within half, 2x4 warps of 64x32 tiles.
__global__ void __launch_bounds__(NTHREADS, 1)
lstm_persist(float* __restrict__ out)
{
    extern __shared__ char smem[];
    const uint32_t sb    = smem_u32(smem);
    const uint32_t base0 = (sb + 1023u) & ~1023u;

    const int tid  = threadIdx.x;
    const int lane = tid & 31;
    const int warp = tid >> 5;
    const int kh   = warp >> 3;             // K-half
    const int wsub = warp & 7;
    const int wm   = (wsub >> 2) * 64;      // warp row offset (batch)
    const int wn   = (wsub & 3) * 32;       // warp col offset (gates)

    const int bx   = blockIdx.x;
    const int band = bx >> 4;
    const int sub  = bx & 15;
    const int n0   = (sub >> 1) * 128;
    const int j0   = (sub >> 1) * 32;
    const int z    = sub & 1;
    const int row0 = band * 128;

    unsigned* barptr = &g_bar[band][0];
    int phase = 0;

    const float *inp = nullptr, *hsrc = nullptr, *W = nullptr;

    float acc[4][4][4];   // 64x32 warp tile: [mt][nt][frag]

    // ---- load both halves' A+B chunk `it` into stage it%3, one commit ------
    auto LOAD = [&](int it) {
        const uint32_t stage = base0 + (it % 3) * STAGEB;
        #pragma unroll
        for (int i = 0; i < 8; i++) {
            int idx = tid + i * NTHREADS;       // 0..4095
            int reg = idx >> 10;                // 0:A0 1:B0 2:A1 3:B1
            int r   = idx & 1023;
            int row = r >> 3;
            int c4  = r & 7;
            int k   = (reg >> 1) * KHALF + it * 32 + c4 * 4;
            uint32_t off = row * 128 + c4 * 16;
            uint32_t sw  = off ^ ((off >> 3) & 0x70);
            uint32_t dst = stage + reg * 16384 + sw;
            const float* src;
            if (reg & 1) {
                src = W + (size_t)(n0 + row) * 768 + k;
            } else {
                src = (k < 512) ? inp  + (size_t)(row0 + row) * 512 + k
                                : hsrc + (size_t)(row0 + row) * 256 + (k - 512);
            }
            asm volatile("cp.async.cg.shared.global [%0], [%1], 16;"
                         :: "r"(dst), "l"(src));
        }
        asm volatile("cp.async.commit_group;" ::: "memory");
    };

    // ---- consumer: this warp's half, 4 k=8 slabs over stage it%3 ------------
    auto COMP = [&](int it) {
        const uint32_t ab = base0 + (it % 3) * STAGEB + kh * 32768;
        const uint32_t bb = ab + 16384;
        #pragma unroll
        for (int kk = 0; kk < 32; kk += 8) {
            uint32_t af[4][4], bf[4][2];
            #pragma unroll
            for (int mt = 0; mt < 4; mt++) {
                int row = wm + mt * 16 + (lane & 15);
                uint32_t off = row * 128 + (lane >> 4) * 16 + kk * 4;
                uint32_t ad = ab + (off ^ ((off >> 3) & 0x70));
                asm volatile(
                    "ldmatrix.sync.aligned.m8n8.x4.shared.b16 {%0,%1,%2,%3}, [%4];"
                    : "=r"(af[mt][0]), "=r"(af[mt][1]),
                      "=r"(af[mt][2]), "=r"(af[mt][3])
                    : "r"(ad));
            }
            #pragma unroll
            for (int ntp = 0; ntp < 2; ntp++) {
                int row = wn + ntp * 16 + ((lane >> 4) & 1) * 8 + (lane & 7);
                uint32_t off = row * 128 + ((lane >> 3) & 1) * 16 + kk * 4;
                uint32_t bd = bb + (off ^ ((off >> 3) & 0x70));
                asm volatile(
                    "ldmatrix.sync.aligned.m8n8.x4.shared.b16 {%0,%1,%2,%3}, [%4];"
                    : "=r"(bf[2 * ntp][0]), "=r"(bf[2 * ntp][1]),
                      "=r"(bf[2 * ntp + 1][0]), "=r"(bf[2 * ntp + 1][1])
                    : "r"(bd));
            }
            #pragma unroll
            for (int mt = 0; mt < 4; mt++)
                #pragma unroll
                for (int nt = 0; nt < 4; nt++)
                    asm volatile(
                        "mma.sync.aligned.m16n8k8.row.col.f32.tf32.tf32.f32 "
                        "{%0,%1,%2,%3}, {%4,%5,%6,%7}, {%8,%9}, {%0,%1,%2,%3};\n"
                        : "+f"(acc[mt][nt][0]), "+f"(acc[mt][nt][1]),
                          "+f"(acc[mt][nt][2]), "+f"(acc[mt][nt][3])
                        : "r"(af[mt][0]), "r"(af[mt][1]),
                          "r"(af[mt][2]), "r"(af[mt][3]),
                          "r"(bf[nt][0]), "r"(bf[nt][1]));
        }
    };

    for (int s = 0; s < NSTEPS; s++) {
        #pragma unroll 1
        for (int layer = 0; layer < 2; layer++) {
            const int lz   = layer * 2 + z;
            const int hsel = s & 1;
            inp  = layer ? &g_x1[0][0] : &g_y[0][0];
            hsrc = &g_hd[hsel][lz][0][0];
            W    = &g_Wp[lz][0][0];

            #pragma unroll
            for (int a = 0; a < 4; a++)
                #pragma unroll
                for (int b = 0; b < 4; b++)
                    #pragma unroll
                    for (int c = 0; c < 4; c++) acc[a][b][c] = 0.f;

            LOAD(0); LOAD(1);
            #pragma unroll 1
            for (int it = 0; it < NITER; it++) {
                if (it < NITER - 1)
                    asm volatile("cp.async.wait_group 1;" ::: "memory");
                else
                    asm volatile("cp.async.wait_group 0;" ::: "memory");
                __syncthreads();
                COMP(it);
                if (it + 2 < NITER) LOAD(it + 2);
            }
            __syncthreads();   // all COMP done before stage smem is reused

            // ---- epilogue: both halves' acc -> smem, combine, cell update ---
            char* gbuf = smem + (base0 - sb) + kh * GBUFB;
            #pragma unroll
            for (int mt = 0; mt < 4; mt++)
                #pragma unroll
                for (int nt = 0; nt < 4; nt++) {
                    int r = wm + mt * 16 + (lane >> 2);
                    int c = wn + nt * 8 + (lane & 3) * 2;
                    *(float2*)(gbuf + (size_t)((r * GSTRIDE + c) * 4)) =
                        make_float2(acc[mt][nt][0], acc[mt][nt][1]);
                    *(float2*)(gbuf + (size_t)(((r + 8) * GSTRIDE + c) * 4)) =
                        make_float2(acc[mt][nt][2], acc[mt][nt][3]);
                }
            __syncthreads();

            char* g0 = smem + (base0 - sb);
            #pragma unroll
            for (int it = 0; it < 8; it++) {
                int idx = tid + it * NTHREADS;      // 0..4095
                int bl  = idx >> 5;
                int jl  = idx & 31;
                size_t boff = (size_t)((bl * GSTRIDE + jl * 4) * 4);
                float4 p0 = *(const float4*)(g0 + boff);
                float4 p1 = *(const float4*)(g0 + GBUFB + boff);
                float4 bs = *(const float4*)&g_bias[lz][(j0 + jl) * 4];
                float gi = p0.x + p1.x + bs.x;
                float gf = p0.y + p1.y + bs.y;
                float gg = p0.z + p1.z + bs.z;
                float go = p0.w + p1.w + bs.w;
                int gb = row0 + bl;
                int j  = j0 + jl;
                float cc = sigf(gf) * g_c[lz][gb][j] + sigf(gi) * tanhf(gg);
                float h  = sigf(go) * tanhf(cc);
                g_c[lz][gb][j] = cc;
                float hr = tf32r(h);
                g_hd[hsel ^ 1][lz][gb][j] = hr;
                if (layer == 0) {
                    g_x1[gb][z * 256 + j] = hr;
                } else {
                    g_y[gb][z * 256 + j] = hr;
                    out[(size_t)gb * (NSTEPS * 512) + (size_t)s * 512 + z * 256 + j] = h;
                }
            }
            __syncthreads();   // epilogue smem reads done before next phase loads

            // ---- band barrier (16 CTAs), monotonic counter ------------------
            const bool last = (s == NSTEPS - 1) && (layer == 1);
            if (!last) {
                phase++;
                if (tid == 0) {
                    unsigned tgt = (unsigned)phase * 16u;
                    unsigned tmp;
                    asm volatile("atom.release.gpu.global.add.u32 %0, [%1], 1;"
                                 : "=r"(tmp) : "l"(barptr) : "memory");
                    unsigned v;
                    do {
                        asm volatile("ld.acquire.gpu.global.u32 %0, [%1];"
                                     : "=r"(v) : "l"(barptr) : "memory");
                        if (v < tgt) __nanosleep(64);
                    } while (v < tgt);
                }
                __syncthreads();
            }
        }
    }
}

// ---------------- weight/bias packing (runs once per launch) ----------------
__global__ void pack_weights(const float* __restrict__ Wih0, const float* __restrict__ Whh0,
                             const float* __restrict__ bih0, const float* __restrict__ bhh0,
                             const float* __restrict__ Wih1, const float* __restrict__ Whh1,
                             const float* __restrict__ bih1, const float* __restrict__ bhh1)
{
    long idx = (long)blockIdx.x * 256 + threadIdx.x;   // 0 .. 4*1024*768-1
    int lz  = (int)(idx / (1024 * 768));
    int rem = (int)(idx % (1024 * 768));
    int r = rem / 768;
    int k = rem % 768;
    int layer = lz >> 1, z = lz & 1;
    int gate = r & 3, j = r >> 2;
    int n = gate * 256 + j;
    const float* Wih = layer ? Wih1 : Wih0;
    const float* Whh = layer ? Whh1 : Whh0;
    float v = (k < 512) ? Wih[((size_t)z * 1024 + n) * 512 + k]
                        : Whh[((size_t)z * 1024 + n) * 256 + (k - 512)];
    g_Wp[lz][r][k] = tf32r(v);

    if (idx < 4096) {
        int blz = (int)(idx >> 10);
        int br  = (int)(idx & 1023);
        int bl = blz >> 1, bz = blz & 1;
        int bg = br & 3, bj = br >> 2;
        const float* bih = bl ? bih1 : bih0;
        const float* bhh = bl ? bhh1 : bhh0;
        g_bias[blz][br] = bih[bz * 1024 + bg * 256 + bj] + bhh[bz * 1024 + bg * 256 + bj];
    }
}

// ---------------- init: code -> (h0, c0); zero feedback; reset barriers -----
__global__ void lstm_init(const float* __restrict__ code)
{
    int idx = blockIdx.x * blockDim.x + threadIdx.x;
    if (idx < BATCH * 2048) {
        int b = idx >> 11;
        int t = idx & 2047;
        float v = code[idx];
        int l = (t >> 8) & 3;
        int j = t & 255;
        if (t < 1024) g_hd[0][l][b][j] = tf32r(v);
        else          g_c[l][b][j] = v;
    } else {
        int r = idx - BATCH * 2048;
        if (r < BATCH * 512) (&g_y[0][0])[r] = 0.f;
    }
    if (idx < 8) g_bar[idx][0] = 0u;
}

// ---------------- launch ----------------------------------------------------
extern "C" void kernel_launch(void* const* d_in, const int* in_sizes, int n_in,
                              void* d_out, int out_size)
{
    const float* code = (const float*)d_in[0];
    // d_in[1] = x : unused by the reference computation
    const float* Wih0 = (const float*)d_in[2];
    const float* Whh0 = (const float*)d_in[3];
    const float* bih0 = (const float*)d_in[4];
    const float* bhh0 = (const float*)d_in[5];
    const float* Wih1 = (const float*)d_in[6];
    const float* Whh1 = (const float*)d_in[7];
    const float* bih1 = (const float*)d_in[8];
    const float* bhh1 = (const float*)d_in[9];
    float* out = (float*)d_out;

    const int smem_bytes = 3 * STAGEB + 1024;   // 197632
    cudaFuncSetAttribute(lstm_persist, cudaFuncAttributeMaxDynamicSharedMemorySize,
                         smem_bytes);

    pack_weights<<<4 * 1024 * 768 / 256, 256>>>(Wih0, Whh0, bih0, bhh0,
                                                Wih1, Whh1, bih1, bhh1);
    lstm_init<<<(BATCH * 2048 + BATCH * 512) / 256, 256>>>(code);

    lstm_persist<<<128, NTHREADS, smem_bytes>>>(out);
}

// round 14
// speedup vs baseline: 1.0987x; 1.0987x over previous
#include <cuda_runtime.h>
#include <math.h>
#include <stdint.h>

#define HID     256
#define NSTEPS  52
#define BATCH   1024

// ---------------- persistent state (device globals; no allocation) ----------
__device__ float g_hd[2][4][BATCH][HID];  // double-buffered h (tf32-rounded)
__device__ float g_c[4][BATCH][HID];      // full fp32 cell state
__device__ float g_y [BATCH][512];        // layer-0 input (prev y, tf32-rounded)
__device__ float g_x1[BATCH][512];        // layer-1 input (concat h, tf32-rounded)
__device__ float g_Wp[4][1024][768];      // packed weights [lz][j*4+gate][k], tf32
__device__ float g_bias[4][1024];         // bih+bhh, packed row order j*4+gate
__device__ unsigned g_bar[8][32];         // per-band barrier counters (128B apart)

// ---------------- helpers ---------------------------------------------------
__device__ __forceinline__ unsigned f2tf32(float x) {
    unsigned u;
    asm("cvt.rna.tf32.f32 %0, %1;" : "=r"(u) : "f"(x));
    return u;
}
__device__ __forceinline__ float tf32r(float x) { return __uint_as_float(f2tf32(x)); }

__device__ __forceinline__ uint32_t smem_u32(const void* p) {
    uint32_t a;
    asm("{ .reg .u64 t; cvta.to.shared.u64 t, %1; cvt.u32.u64 %0, t; }" : "=r"(a) : "l"(p));
    return a;
}
__device__ __forceinline__ float rcpf(float x) {
    float r;
    asm("rcp.approx.f32 %0, %1;" : "=f"(r) : "f"(x));
    return r;
}
__device__ __forceinline__ float sigf(float x)  { return rcpf(1.f + __expf(-x)); }
__device__ __forceinline__ float tanhfast(float x) {
    return 1.f - 2.f * rcpf(1.f + __expf(2.f * x));
}

#define NTHREADS 512
#define NPAIR   12             // K=768 in 12 pairs of 2x32 chunks
#define STAGEB  65536          // one stage: [A0 16K][B0 16K][A1 16K][B1 16K]
#define GSTRIDE 132            // epilogue gate smem row stride (floats), padded

// ---------------- persistent fused LSTM kernel ------------------------------
// 128 CTAs (<=148 SMs -> co-resident). CTA bx: band=bx>>4 (batch rows band*128),
// sub=bx&15: n0=(sub>>1)*128 (gate-row tile), z=sub&1 (direction).
// 16 warps, 4x4 layout, each warp a 32x32 output tile over full K.
__global__ void __launch_bounds__(NTHREADS, 1)
lstm_persist(float* __restrict__ out)
{
    extern __shared__ char smem[];
    const uint32_t sb    = smem_u32(smem);
    const uint32_t base0 = (sb + 1023u) & ~1023u;

    const int tid  = threadIdx.x;
    const int lane = tid & 31;
    const int warp = tid >> 5;
    const int wm   = (warp >> 2) * 32;      // warp row offset (batch)
    const int wn   = (warp & 3) * 32;       // warp col offset (gates)
    const int rot  = (warp & 3) * 2;        // slab start rotation (de-convoy)

    const int bx   = blockIdx.x;
    const int band = bx >> 4;
    const int sub  = bx & 15;
    const int n0   = (sub >> 1) * 128;
    const int j0   = (sub >> 1) * 32;
    const int z    = sub & 1;
    const int row0 = band * 128;

    unsigned* barptr = &g_bar[band][0];
    int phase = 0;

    const float *inp = nullptr, *hsrc = nullptr, *W = nullptr;

    float acc[2][4][4];   // 32x32 warp tile

    // ---- load pair p (chunks 2p, 2p+1) into stage p%3; one commit ----------
    // withB=false skips the B halves (already prefetched over the barrier).
    auto LOADPAIR = [&](int p, bool withB) {
        const uint32_t stage = base0 + (p % 3) * STAGEB;
        #pragma unroll
        for (int c = 0; c < 2; c++) {
            const int k0 = (2 * p + c) * 32;
            const uint32_t abase = stage + c * 32768;
            #pragma unroll
            for (int i = 0; i < 2; i++) {
                int idx = tid + i * NTHREADS;       // 0..1023
                int row = idx >> 3;
                int c4  = idx & 7;
                int k   = k0 + c4 * 4;
                uint32_t off = row * 128 + c4 * 16;
                uint32_t sw  = off ^ ((off >> 3) & 0x70);
                const float* asrc = (k < 512)
                    ? inp  + (size_t)(row0 + row) * 512 + k
                    : hsrc + (size_t)(row0 + row) * 256 + (k - 512);
                asm volatile("cp.async.cg.shared.global [%0], [%1], 16;"
                             :: "r"(abase + sw), "l"(asrc));
                if (withB) {
                    const float* bsrc = W + (size_t)(n0 + row) * 768 + k;
                    asm volatile("cp.async.cg.shared.global [%0], [%1], 16;"
                                 :: "r"(abase + 16384 + sw), "l"(bsrc));
                }
            }
        }
        asm volatile("cp.async.commit_group;" ::: "memory");
    };

    // ---- B-only prefetch of pair 0 for the NEXT phase (uncommitted) --------
    auto PREFB0 = [&](const float* Wn) {
        #pragma unroll
        for (int c = 0; c < 2; c++) {
            const int k0 = c * 32;
            const uint32_t bbase = base0 + c * 32768 + 16384;
            #pragma unroll
            for (int i = 0; i < 2; i++) {
                int idx = tid + i * NTHREADS;
                int row = idx >> 3;
                int c4  = idx & 7;
                uint32_t off = row * 128 + c4 * 16;
                uint32_t sw  = off ^ ((off >> 3) & 0x70);
                const float* bsrc = Wn + (size_t)(n0 + row) * 768 + k0 + c4 * 4;
                asm volatile("cp.async.cg.shared.global [%0], [%1], 16;"
                             :: "r"(bbase + sw), "l"(bsrc));
            }
        }
    };

    // ---- fragment fetch for slab s (0..7) of stage p ------------------------
    auto LDFRAG = [&](uint32_t stage, int s,
                      uint32_t (&af)[2][4], uint32_t (&bf)[4][2]) {
        const uint32_t ab = stage + (s >> 2) * 32768;
        const uint32_t bb = ab + 16384;
        const int kk = (s & 3) * 8;
        #pragma unroll
        for (int mt = 0; mt < 2; mt++) {
            int row = wm + mt * 16 + (lane & 15);
            uint32_t off = row * 128 + (lane >> 4) * 16 + kk * 4;
            uint32_t ad = ab + (off ^ ((off >> 3) & 0x70));
            asm volatile(
                "ldmatrix.sync.aligned.m8n8.x4.shared.b16 {%0,%1,%2,%3}, [%4];"
                : "=r"(af[mt][0]), "=r"(af[mt][1]),
                  "=r"(af[mt][2]), "=r"(af[mt][3])
                : "r"(ad));
        }
        #pragma unroll
        for (int ntp = 0; ntp < 2; ntp++) {
            int row = wn + ntp * 16 + ((lane >> 4) & 1) * 8 + (lane & 7);
            uint32_t off = row * 128 + ((lane >> 3) & 1) * 16 + kk * 4;
            uint32_t bd = bb + (off ^ ((off >> 3) & 0x70));
            asm volatile(
                "ldmatrix.sync.aligned.m8n8.x4.shared.b16 {%0,%1,%2,%3}, [%4];"
                : "=r"(bf[2 * ntp][0]), "=r"(bf[2 * ntp][1]),
                  "=r"(bf[2 * ntp + 1][0]), "=r"(bf[2 * ntp + 1][1])
                : "r"(bd));
        }
    };

    // ---- consumer: 8 slabs of stage p, rotated start, frag double-buffer ----
    auto COMP = [&](int p) {
        const uint32_t stage = base0 + (p % 3) * STAGEB;
        uint32_t af[2][2][4], bf[2][4][2];
        LDFRAG(stage, rot, af[0], bf[0]);
        #pragma unroll
        for (int sl = 0; sl < 8; sl++) {
            const int cur = sl & 1;
            if (sl < 7) LDFRAG(stage, (rot + sl + 1) & 7, af[cur ^ 1], bf[cur ^ 1]);
            #pragma unroll
            for (int mt = 0; mt < 2; mt++)
                #pragma unroll
                for (int nt = 0; nt < 4; nt++)
                    asm volatile(
                        "mma.sync.aligned.m16n8k8.row.col.f32.tf32.tf32.f32 "
                        "{%0,%1,%2,%3}, {%4,%5,%6,%7}, {%8,%9}, {%0,%1,%2,%3};\n"
                        : "+f"(acc[mt][nt][0]), "+f"(acc[mt][nt][1]),
                          "+f"(acc[mt][nt][2]), "+f"(acc[mt][nt][3])
                        : "r"(af[cur][mt][0]), "r"(af[cur][mt][1]),
                          "r"(af[cur][mt][2]), "r"(af[cur][mt][3]),
                          "r"(bf[cur][nt][0]), "r"(bf[cur][nt][1]));
        }
    };

    bool bPrefetched = false;

    for (int s = 0; s < NSTEPS; s++) {
        #pragma unroll 1
        for (int layer = 0; layer < 2; layer++) {
            const int lz   = layer * 2 + z;
            const int hsel = s & 1;
            inp  = layer ? &g_x1[0][0] : &g_y[0][0];
            hsrc = &g_hd[hsel][lz][0][0];
            W    = &g_Wp[lz][0][0];

            #pragma unroll
            for (int a = 0; a < 2; a++)
                #pragma unroll
                for (int b = 0; b < 4; b++)
                    #pragma unroll
                    for (int c = 0; c < 4; c++) acc[a][b][c] = 0.f;

            LOADPAIR(0, !bPrefetched);
            LOADPAIR(1, true);
            #pragma unroll 1
            for (int it = 0; it < NPAIR; it++) {
                if (it < NPAIR - 1)
                    asm volatile("cp.async.wait_group 1;" ::: "memory");
                else
                    asm volatile("cp.async.wait_group 0;" ::: "memory");
                __syncthreads();
                COMP(it);
                if (it + 2 < NPAIR) LOADPAIR(it + 2, true);
            }
            __syncthreads();   // all COMP done before stage smem is reused

            // ---- epilogue: acc -> padded smem, fused cell update ------------
            char* gptr = smem + (base0 - sb);
            #pragma unroll
            for (int mt = 0; mt < 2; mt++)
                #pragma unroll
                for (int nt = 0; nt < 4; nt++) {
                    int r = wm + mt * 16 + (lane >> 2);
                    int c = wn + nt * 8 + (lane & 3) * 2;
                    *(float2*)(gptr + (size_t)((r * GSTRIDE + c) * 4)) =
                        make_float2(acc[mt][nt][0], acc[mt][nt][1]);
                    *(float2*)(gptr + (size_t)(((r + 8) * GSTRIDE + c) * 4)) =
                        make_float2(acc[mt][nt][2], acc[mt][nt][3]);
                }
            __syncthreads();

            #pragma unroll
            for (int it = 0; it < 8; it++) {
                int idx = tid + it * NTHREADS;      // 0..4095
                int bl  = idx >> 5;
                int jl  = idx & 31;
                float4 g4 = *(const float4*)(gptr + (size_t)((bl * GSTRIDE + jl * 4) * 4));
                float4 bs = *(const float4*)&g_bias[lz][(j0 + jl) * 4];
                int gb = row0 + bl;
                int j  = j0 + jl;
                float cc = sigf(g4.y + bs.y) * g_c[lz][gb][j]
                         + sigf(g4.x + bs.x) * tanhfast(g4.z + bs.z);
                float h  = sigf(g4.w + bs.w) * tanhfast(cc);
                g_c[lz][gb][j] = cc;
                float hr = tf32r(h);
                g_hd[hsel ^ 1][lz][gb][j] = hr;
                if (layer == 0) {
                    g_x1[gb][z * 256 + j] = hr;
                } else {
                    g_y[gb][z * 256 + j] = hr;
                    out[(size_t)gb * (NSTEPS * 512) + (size_t)s * 512 + z * 256 + j] = h;
                }
            }
            __syncthreads();   // epilogue smem reads done before prefetch reuses it

            // ---- prefetch next phase's stage-0 B, then band barrier ---------
            const bool last = (s == NSTEPS - 1) && (layer == 1);
            if (!last) {
                const float* Wn = (layer == 0) ? &g_Wp[2 + z][0][0] : &g_Wp[z][0][0];
                PREFB0(Wn);
                bPrefetched = true;

                phase++;
                if (tid == 0) {
                    unsigned tgt = (unsigned)phase * 16u;
                    unsigned tmp;
                    asm volatile("atom.release.gpu.global.add.u32 %0, [%1], 1;"
                                 : "=r"(tmp) : "l"(barptr) : "memory");
                    unsigned v;
                    do {
                        asm volatile("ld.acquire.gpu.global.u32 %0, [%1];"
                                     : "=r"(v) : "l"(barptr) : "memory");
                    } while (v < tgt);
                }
                __syncthreads();
            }
        }
    }
}

// ---------------- weight/bias packing (runs once per launch) ----------------
__global__ void pack_weights(const float* __restrict__ Wih0, const float* __restrict__ Whh0,
                             const float* __restrict__ bih0, const float* __restrict__ bhh0,
                             const float* __restrict__ Wih1, const float* __restrict__ Whh1,
                             const float* __restrict__ bih1, const float* __restrict__ bhh1)
{
    long idx = (long)blockIdx.x * 256 + threadIdx.x;   // 0 .. 4*1024*768-1
    int lz  = (int)(idx / (1024 * 768));
    int rem = (int)(idx % (1024 * 768));
    int r = rem / 768;
    int k = rem % 768;
    int layer = lz >> 1, z = lz & 1;
    int gate = r & 3, j = r >> 2;
    int n = gate * 256 + j;
    const float* Wih = layer ? Wih1 : Wih0;
    const float* Whh = layer ? Whh1 : Whh0;
    float v = (k < 512) ? Wih[((size_t)z * 1024 + n) * 512 + k]
                        : Whh[((size_t)z * 1024 + n) * 256 + (k - 512)];
    g_Wp[lz][r][k] = tf32r(v);

    if (idx < 4096) {
        int blz = (int)(idx >> 10);
        int br  = (int)(idx & 1023);
        int bl = blz >> 1, bz = blz & 1;
        int bg = br & 3, bj = br >> 2;
        const float* bih = bl ? bih1 : bih0;
        const float* bhh = bl ? bhh1 : bhh0;
        g_bias[blz][br] = bih[bz * 1024 + bg * 256 + bj] + bhh[bz * 1024 + bg * 256 + bj];
    }
}

// ---------------- init: code -> (h0, c0); zero feedback; reset barriers -----
__global__ void lstm_init(const float* __restrict__ code)
{
    int idx = blockIdx.x * blockDim.x + threadIdx.x;
    if (idx < BATCH * 2048) {
        int b = idx >> 11;
        int t = idx & 2047;
        float v = code[idx];
        int l = (t >> 8) & 3;
        int j = t & 255;
        if (t < 1024) g_hd[0][l][b][j] = tf32r(v);
        else          g_c[l][b][j] = v;
    } else {
        int r = idx - BATCH * 2048;
        if (r < BATCH * 512) (&g_y[0][0])[r] = 0.f;
    }
    if (idx < 8) g_bar[idx][0] = 0u;
}

// ---------------- launch ----------------------------------------------------
extern "C" void kernel_launch(void* const* d_in, const int* in_sizes, int n_in,
                              void* d_out, int out_size)
{
    const float* code = (const float*)d_in[0];
    // d_in[1] = x : unused by the reference computation
    const float* Wih0 = (const float*)d_in[2];
    const float* Whh0 = (const float*)d_in[3];
    const float* bih0 = (const float*)d_in[4];
    const float* bhh0 = (const float*)d_in[5];
    const float* Wih1 = (const float*)d_in[6];
    const float* Whh1 = (const float*)d_in[7];
    const float* bih1 = (const float*)d_in[8];
    const float* bhh1 = (const float*)d_in[9];
    float* out = (float*)d_out;

    const int smem_bytes = 3 * STAGEB + 1024;   // 197632
    cudaFuncSetAttribute(lstm_persist, cudaFuncAttributeMaxDynamicSharedMemorySize,
                         smem_bytes);

    pack_weights<<<4 * 1024 * 768 / 256, 256>>>(Wih0, Whh0, bih0, bhh0,
                                                Wih1, Whh1, bih1, bhh1);
    lstm_init<<<(BATCH * 2048 + BATCH * 512) / 256, 256>>>(code);

    lstm_persist<<<128, NTHREADS, smem_bytes>>>(out);
}

// round 15
// speedup vs baseline: 1.1824x; 1.0762x over previous
#include <cuda_runtime.h>
#include <cuda_fp16.h>
#include <math.h>
#include <stdint.h>

#define HID     256
#define NSTEPS  52
#define BATCH   1024

// ---------------- persistent state (device globals; no allocation) ----------
__device__ __align__(16) __half g_hd[2][4][BATCH][HID]; // double-buffered h (fp16)
__device__ float  g_c[4][BATCH][HID];                   // full fp32 cell state
__device__ __align__(16) __half g_y [BATCH][512];       // layer-0 input (prev y)
__device__ __align__(16) __half g_x1[BATCH][512];       // layer-1 input (concat h)
__device__ __align__(16) __half g_Wp[4][1024][768];     // packed fp16 weights
__device__ float  g_bias[4][1024];                      // bih+bhh, row order j*4+gate
__device__ unsigned g_bar[8][32];                       // per-band barrier counters

// ---------------- helpers ---------------------------------------------------
__device__ __forceinline__ uint32_t smem_u32(const void* p) {
    uint32_t a;
    asm("{ .reg .u64 t; cvta.to.shared.u64 t, %1; cvt.u32.u64 %0, t; }" : "=r"(a) : "l"(p));
    return a;
}
__device__ __forceinline__ float rcpf(float x) {
    float r;
    asm("rcp.approx.f32 %0, %1;" : "=f"(r) : "f"(x));
    return r;
}
__device__ __forceinline__ float sigf(float x)  { return rcpf(1.f + __expf(-x)); }
__device__ __forceinline__ float tanhfast(float x) {
    return 1.f - 2.f * rcpf(1.f + __expf(2.f * x));
}

#define NTHREADS 512
#define NPAIR   6              // K=768 in 6 pairs of 2x64 k-chunks
#define CHUNKB  32768          // one chunk: [A 16K][B 16K] (128 rows x 128B each)
#define STAGEB  65536          // one stage: 2 chunks
#define GSTRIDE 132            // epilogue gate smem row stride (floats), padded

// ---------------- persistent fused LSTM kernel ------------------------------
// 128 CTAs (<=148 SMs -> co-resident). CTA bx: band=bx>>4 (batch rows band*128),
// sub=bx&15: n0=(sub>>1)*128 (gate-row tile), z=sub&1 (direction).
// 16 warps, 4x4 layout, each warp a 32x32 output tile over full K. fp16 MMA k16.
__global__ void __launch_bounds__(NTHREADS, 1)
lstm_persist(float* __restrict__ out)
{
    extern __shared__ char smem[];
    const uint32_t sb    = smem_u32(smem);
    const uint32_t base0 = (sb + 1023u) & ~1023u;

    const int tid  = threadIdx.x;
    const int lane = tid & 31;
    const int warp = tid >> 5;
    const int wm   = (warp >> 2) * 32;      // warp row offset (batch)
    const int wn   = (warp & 3) * 32;       // warp col offset (gates)
    const int rot  = (warp & 3) * 2;        // slab start rotation (de-convoy)

    const int bx   = blockIdx.x;
    const int band = bx >> 4;
    const int sub  = bx & 15;
    const int n0   = (sub >> 1) * 128;
    const int j0   = (sub >> 1) * 32;
    const int z    = sub & 1;
    const int row0 = band * 128;

    unsigned* barptr = &g_bar[band][0];
    int phase = 0;

    const __half *inp = nullptr, *hsrc = nullptr, *W = nullptr;

    float acc[2][4][4];   // 32x32 warp tile

    // ---- load pair p (k-chunks 2p, 2p+1) into stage p%3; one commit --------
    auto LOADPAIR = [&](int p, bool withB) {
        const uint32_t stage = base0 + (p % 3) * STAGEB;
        #pragma unroll
        for (int c = 0; c < 2; c++) {
            const int k0 = (2 * p + c) * 64;         // k element offset
            const uint32_t abase = stage + c * CHUNKB;
            #pragma unroll
            for (int i = 0; i < 2; i++) {
                int idx = tid + i * NTHREADS;        // 0..1023
                int row = idx >> 3;
                int c8  = idx & 7;                   // 16B segment (8 fp16)
                int k   = k0 + c8 * 8;
                uint32_t off = row * 128 + c8 * 16;
                uint32_t sw  = off ^ ((off >> 3) & 0x70);
                const __half* asrc = (k < 512)
                    ? inp  + (size_t)(row0 + row) * 512 + k
                    : hsrc + (size_t)(row0 + row) * 256 + (k - 512);
                asm volatile("cp.async.cg.shared.global [%0], [%1], 16;"
                             :: "r"(abase + sw), "l"(asrc));
                if (withB) {
                    const __half* bsrc = W + (size_t)(n0 + row) * 768 + k;
                    asm volatile("cp.async.cg.shared.global [%0], [%1], 16;"
                                 :: "r"(abase + 16384 + sw), "l"(bsrc));
                }
            }
        }
        asm volatile("cp.async.commit_group;" ::: "memory");
    };

    // ---- B-only prefetch of pair 0 for the NEXT phase (uncommitted) --------
    auto PREFB0 = [&](const __half* Wn) {
        #pragma unroll
        for (int c = 0; c < 2; c++) {
            const int k0 = c * 64;
            const uint32_t bbase = base0 + c * CHUNKB + 16384;
            #pragma unroll
            for (int i = 0; i < 2; i++) {
                int idx = tid + i * NTHREADS;
                int row = idx >> 3;
                int c8  = idx & 7;
                uint32_t off = row * 128 + c8 * 16;
                uint32_t sw  = off ^ ((off >> 3) & 0x70);
                const __half* bsrc = Wn + (size_t)(n0 + row) * 768 + k0 + c8 * 8;
                asm volatile("cp.async.cg.shared.global [%0], [%1], 16;"
                             :: "r"(bbase + sw), "l"(bsrc));
            }
        }
    };

    // ---- fragment fetch for k16 slab s (0..7) of stage ----------------------
    auto LDFRAG = [&](uint32_t stage, int s,
                      uint32_t (&af)[2][4], uint32_t (&bf)[4][2]) {
        const uint32_t ab = stage + (s >> 2) * CHUNKB;
        const uint32_t bb = ab + 16384;
        const int kb = (s & 3) * 32;                 // slab byte offset (16 fp16)
        #pragma unroll
        for (int mt = 0; mt < 2; mt++) {
            int row = wm + mt * 16 + (lane & 15);
            uint32_t off = row * 128 + (lane >> 4) * 16 + kb;
            uint32_t ad = ab + (off ^ ((off >> 3) & 0x70));
            asm volatile(
                "ldmatrix.sync.aligned.m8n8.x4.shared.b16 {%0,%1,%2,%3}, [%4];"
                : "=r"(af[mt][0]), "=r"(af[mt][1]),
                  "=r"(af[mt][2]), "=r"(af[mt][3])
                : "r"(ad));
        }
        #pragma unroll
        for (int ntp = 0; ntp < 2; ntp++) {
            int row = wn + ntp * 16 + ((lane >> 4) & 1) * 8 + (lane & 7);
            uint32_t off = row * 128 + ((lane >> 3) & 1) * 16 + kb;
            uint32_t bd = bb + (off ^ ((off >> 3) & 0x70));
            asm volatile(
                "ldmatrix.sync.aligned.m8n8.x4.shared.b16 {%0,%1,%2,%3}, [%4];"
                : "=r"(bf[2 * ntp][0]), "=r"(bf[2 * ntp][1]),
                  "=r"(bf[2 * ntp + 1][0]), "=r"(bf[2 * ntp + 1][1])
                : "r"(bd));
        }
    };

    // ---- consumer: 8 k16 slabs of stage p, rotated, frag double-buffer ------
    auto COMP = [&](int p) {
        const uint32_t stage = base0 + (p % 3) * STAGEB;
        uint32_t af[2][2][4], bf[2][4][2];
        LDFRAG(stage, rot, af[0], bf[0]);
        #pragma unroll
        for (int sl = 0; sl < 8; sl++) {
            const int cur = sl & 1;
            if (sl < 7) LDFRAG(stage, (rot + sl + 1) & 7, af[cur ^ 1], bf[cur ^ 1]);
            #pragma unroll
            for (int mt = 0; mt < 2; mt++)
                #pragma unroll
                for (int nt = 0; nt < 4; nt++)
                    asm volatile(
                        "mma.sync.aligned.m16n8k16.row.col.f32.f16.f16.f32 "
                        "{%0,%1,%2,%3}, {%4,%5,%6,%7}, {%8,%9}, {%0,%1,%2,%3};\n"
                        : "+f"(acc[mt][nt][0]), "+f"(acc[mt][nt][1]),
                          "+f"(acc[mt][nt][2]), "+f"(acc[mt][nt][3])
                        : "r"(af[cur][mt][0]), "r"(af[cur][mt][1]),
                          "r"(af[cur][mt][2]), "r"(af[cur][mt][3]),
                          "r"(bf[cur][nt][0]), "r"(bf[cur][nt][1]));
        }
    };

    bool bPrefetched = false;

    for (int s = 0; s < NSTEPS; s++) {
        #pragma unroll 1
        for (int layer = 0; layer < 2; layer++) {
            const int lz   = layer * 2 + z;
            const int hsel = s & 1;
            inp  = layer ? &g_x1[0][0] : &g_y[0][0];
            hsrc = &g_hd[hsel][lz][0][0];
            W    = &g_Wp[lz][0][0];

            #pragma unroll
            for (int a = 0; a < 2; a++)
                #pragma unroll
                for (int b = 0; b < 4; b++)
                    #pragma unroll
                    for (int c = 0; c < 4; c++) acc[a][b][c] = 0.f;

            LOADPAIR(0, !bPrefetched);
            LOADPAIR(1, true);
            #pragma unroll 1
            for (int it = 0; it < NPAIR; it++) {
                if (it < NPAIR - 1)
                    asm volatile("cp.async.wait_group 1;" ::: "memory");
                else
                    asm volatile("cp.async.wait_group 0;" ::: "memory");
                __syncthreads();
                COMP(it);
                if (it + 2 < NPAIR) LOADPAIR(it + 2, true);
            }
            __syncthreads();   // all COMP done before stage smem is reused

            // ---- epilogue: acc -> padded smem, fused cell update ------------
            char* gptr = smem + (base0 - sb);
            #pragma unroll
            for (int mt = 0; mt < 2; mt++)
                #pragma unroll
                for (int nt = 0; nt < 4; nt++) {
                    int r = wm + mt * 16 + (lane >> 2);
                    int c = wn + nt * 8 + (lane & 3) * 2;
                    *(float2*)(gptr + (size_t)((r * GSTRIDE + c) * 4)) =
                        make_float2(acc[mt][nt][0], acc[mt][nt][1]);
                    *(float2*)(gptr + (size_t)(((r + 8) * GSTRIDE + c) * 4)) =
                        make_float2(acc[mt][nt][2], acc[mt][nt][3]);
                }
            __syncthreads();

            #pragma unroll
            for (int it = 0; it < 8; it++) {
                int idx = tid + it * NTHREADS;      // 0..4095
                int bl  = idx >> 5;
                int jl  = idx & 31;
                float4 g4 = *(const float4*)(gptr + (size_t)((bl * GSTRIDE + jl * 4) * 4));
                float4 bs = *(const float4*)&g_bias[lz][(j0 + jl) * 4];
                int gb = row0 + bl;
                int j  = j0 + jl;
                float cc = sigf(g4.y + bs.y) * g_c[lz][gb][j]
                         + sigf(g4.x + bs.x) * tanhfast(g4.z + bs.z);
                float h  = sigf(g4.w + bs.w) * tanhfast(cc);
                g_c[lz][gb][j] = cc;
                __half hh = __float2half(h);
                g_hd[hsel ^ 1][lz][gb][j] = hh;
                if (layer == 0) {
                    g_x1[gb][z * 256 + j] = hh;
                } else {
                    g_y[gb][z * 256 + j] = hh;
                    out[(size_t)gb * (NSTEPS * 512) + (size_t)s * 512 + z * 256 + j] = h;
                }
            }
            __syncthreads();   // epilogue smem reads done before prefetch reuses it

            // ---- prefetch next phase's pair-0 B, then band barrier ----------
            const bool last = (s == NSTEPS - 1) && (layer == 1);
            if (!last) {
                const __half* Wn = (layer == 0) ? &g_Wp[2 + z][0][0] : &g_Wp[z][0][0];
                PREFB0(Wn);
                bPrefetched = true;

                phase++;
                if (tid == 0) {
                    unsigned tgt = (unsigned)phase * 16u;
                    unsigned tmp;
                    asm volatile("atom.release.gpu.global.add.u32 %0, [%1], 1;"
                                 : "=r"(tmp) : "l"(barptr) : "memory");
                    unsigned v;
                    do {
                        asm volatile("ld.acquire.gpu.global.u32 %0, [%1];"
                                     : "=r"(v) : "l"(barptr) : "memory");
                    } while (v < tgt);
                }
                __syncthreads();
            }
        }
    }
}

// ---------------- weight/bias packing (runs once per launch) ----------------
__global__ void pack_weights(const float* __restrict__ Wih0, const float* __restrict__ Whh0,
                             const float* __restrict__ bih0, const float* __restrict__ bhh0,
                             const float* __restrict__ Wih1, const float* __restrict__ Whh1,
                             const float* __restrict__ bih1, const float* __restrict__ bhh1)
{
    long idx = (long)blockIdx.x * 256 + threadIdx.x;   // 0 .. 4*1024*768-1
    int lz  = (int)(idx / (1024 * 768));
    int rem = (int)(idx % (1024 * 768));
    int r = rem / 768;
    int k = rem % 768;
    int layer = lz >> 1, z = lz & 1;
    int gate = r & 3, j = r >> 2;
    int n = gate * 256 + j;
    const float* Wih = layer ? Wih1 : Wih0;
    const float* Whh = layer ? Whh1 : Whh0;
    float v = (k < 512) ? Wih[((size_t)z * 1024 + n) * 512 + k]
                        : Whh[((size_t)z * 1024 + n) * 256 + (k - 512)];
    g_Wp[lz][r][k] = __float2half(v);

    if (idx < 4096) {
        int blz = (int)(idx >> 10);
        int br  = (int)(idx & 1023);
        int bl = blz >> 1, bz = blz & 1;
        int bg = br & 3, bj = br >> 2;
        const float* bih = bl ? bih1 : bih0;
        const float* bhh = bl ? bhh1 : bhh0;
        g_bias[blz][br] = bih[bz * 1024 + bg * 256 + bj] + bhh[bz * 1024 + bg * 256 + bj];
    }
}

// ---------------- init: code -> (h0, c0); zero feedback; reset barriers -----
__global__ void lstm_init(const float* __restrict__ code)
{
    int idx = blockIdx.x * blockDim.x + threadIdx.x;
    if (idx < BATCH * 2048) {
        int b = idx >> 11;
        int t = idx & 2047;
        float v = code[idx];
        int l = (t >> 8) & 3;
        int j = t & 255;
        if (t < 1024) g_hd[0][l][b][j] = __float2half(v);
        else          g_c[l][b][j] = v;
    } else {
        int r = idx - BATCH * 2048;
        if (r < BATCH * 512) (&g_y[0][0])[r] = __float2half(0.f);
    }
    if (idx < 8) g_bar[idx][0] = 0u;
}

// ---------------- launch ----------------------------------------------------
extern "C" void kernel_launch(void* const* d_in, const int* in_sizes, int n_in,
                              void* d_out, int out_size)
{
    const float* code = (const float*)d_in[0];
    // d_in[1] = x : unused by the reference computation
    const float* Wih0 = (const float*)d_in[2];
    const float* Whh0 = (const float*)d_in[3];
    const float* bih0 = (const float*)d_in[4];
    const float* bhh0 = (const float*)d_in[5];
    const float* Wih1 = (const float*)d_in[6];
    const float* Whh1 = (const float*)d_in[7];
    const float* bih1 = (const float*)d_in[8];
    const float* bhh1 = (const float*)d_in[9];
    float* out = (float*)d_out;

    const int smem_bytes = 3 * STAGEB + 1024;   // 197632
    cudaFuncSetAttribute(lstm_persist, cudaFuncAttributeMaxDynamicSharedMemorySize,
                         smem_bytes);

    pack_weights<<<4 * 1024 * 768 / 256, 256>>>(Wih0, Whh0, bih0, bhh0,
                                                Wih1, Whh1, bih1, bhh1);
    lstm_init<<<(BATCH * 2048 + BATCH * 512) / 256, 256>>>(code);

    lstm_persist<<<128, NTHREADS, smem_bytes>>>(out);
}

// round 16
// speedup vs baseline: 1.9555x; 1.6537x over previous
#include <cuda_runtime.h>
#include <cuda_fp16.h>
#include <math.h>
#include <stdint.h>

#define HID     256
#define NSTEPS  52
#define BATCH   1024

// ---------------- persistent state (device globals; no allocation) ----------
__device__ __align__(16) __half g_hd[2][4][BATCH][HID]; // double-buffered h (fp16)
__device__ float  g_c[4][BATCH][HID];                   // full fp32 cell state
__device__ __align__(16) __half g_y [BATCH][512];       // layer-0 input (prev y)
__device__ __align__(16) __half g_x1[BATCH][512];       // layer-1 input (concat h)
__device__ __align__(16) __half g_Wp[4][1024][768];     // packed fp16 weights
__device__ float  g_bias[4][1024];                      // bih+bhh, row order j*4+gate
__device__ unsigned g_bar[8][32];                       // per-band barrier counters

// ---------------- helpers ---------------------------------------------------
__device__ __forceinline__ uint32_t smem_u32(const void* p) {
    uint32_t a;
    asm("{ .reg .u64 t; cvta.to.shared.u64 t, %1; cvt.u32.u64 %0, t; }" : "=r"(a) : "l"(p));
    return a;
}
__device__ __forceinline__ float rcpf(float x) {
    float r;
    asm("rcp.approx.f32 %0, %1;" : "=f"(r) : "f"(x));
    return r;
}
__device__ __forceinline__ float sigf(float x)  { return rcpf(1.f + __expf(-x)); }
__device__ __forceinline__ float tanhfast(float x) {
    return 1.f - 2.f * rcpf(1.f + __expf(2.f * x));
}

#define NTHREADS 512
#define CHUNKB  32768          // one k-chunk slot: [A 16K][B 16K]
#define STAGEB  65536          // one stage: 2 chunks (one pair)
#define GSTRIDE 132            // epilogue gate smem row stride (floats), padded

// ---------------- persistent fused LSTM kernel ------------------------------
// 128 CTAs (<=148 SMs -> co-resident). CTA bx: band=bx>>4 (batch rows band*128),
// sub=bx&15: n0=(sub>>1)*128 (gate-row tile), z=sub&1 (direction).
// 16 warps, 4x4 layout, each warp a 32x32 output tile over full K. fp16 MMA k16.
// K=768 in 12 chunks of 64; pairs p = chunks {2p,2p+1} -> stage p%3.
// Pair consumption order {4,5,0,1,2,3}: pairs 4,5 (h-part A + B) and B of pair 0
// are prefetched OVER the inter-CTA barrier (h is 2 phases old -> safe).
__global__ void __launch_bounds__(NTHREADS, 1)
lstm_persist(float* __restrict__ out)
{
    extern __shared__ char smem[];
    const uint32_t sb    = smem_u32(smem);
    const uint32_t base0 = (sb + 1023u) & ~1023u;

    const int tid  = threadIdx.x;
    const int lane = tid & 31;
    const int warp = tid >> 5;
    const int wm   = (warp >> 2) * 32;      // warp row offset (batch)
    const int wn   = (warp & 3) * 32;       // warp col offset (gates)
    const int rot  = (warp & 3) * 2;        // slab start rotation (de-convoy)

    const int bx   = blockIdx.x;
    const int band = bx >> 4;
    const int sub  = bx & 15;
    const int n0   = (sub >> 1) * 128;
    const int j0   = (sub >> 1) * 32;
    const int z    = sub & 1;
    const int row0 = band * 128;

    unsigned* barptr = &g_bar[band][0];
    int phase = 0;

    float acc[2][4][4];   // 32x32 warp tile

    // ---- chunk loaders: chunk c -> stage (c>>1)%3, half c&1 -----------------
    // A from `src` (row stride `width` halfs, k offset kbase within src row).
    auto LOAD_A = [&](int c, const __half* src, int width, int kbase) {
        const uint32_t ab = base0 + ((c >> 1) % 3) * STAGEB + (c & 1) * CHUNKB;
        #pragma unroll
        for (int i = 0; i < 2; i++) {
            int idx = tid + i * NTHREADS;        // 0..1023
            int row = idx >> 3;
            int c8  = idx & 7;
            uint32_t off = row * 128 + c8 * 16;
            uint32_t sw  = off ^ ((off >> 3) & 0x70);
            const __half* s = src + (size_t)(row0 + row) * width + kbase + c8 * 8;
            asm volatile("cp.async.cg.shared.global [%0], [%1], 16;"
                         :: "r"(ab + sw), "l"(s));
        }
    };
    auto LOAD_B = [&](int c, const __half* Wsrc) {
        const uint32_t bb = base0 + ((c >> 1) % 3) * STAGEB + (c & 1) * CHUNKB + 16384;
        #pragma unroll
        for (int i = 0; i < 2; i++) {
            int idx = tid + i * NTHREADS;
            int row = idx >> 3;
            int c8  = idx & 7;
            uint32_t off = row * 128 + c8 * 16;
            uint32_t sw  = off ^ ((off >> 3) & 0x70);
            const __half* s = Wsrc + (size_t)(n0 + row) * 768 + c * 64 + c8 * 8;
            asm volatile("cp.async.cg.shared.global [%0], [%1], 16;"
                         :: "r"(bb + sw), "l"(s));
        }
    };

    // ---- prefetch group for a phase: B(0,1) + A+B(8..11); one commit --------
    auto PREF = [&](const __half* h_, const __half* W_) {
        LOAD_B(0, W_); LOAD_B(1, W_);
        #pragma unroll
        for (int c = 8; c < 12; c++) {
            LOAD_A(c, h_, 256, c * 64 - 512);
            LOAD_B(c, W_);
        }
        asm volatile("cp.async.commit_group;" ::: "memory");
    };

    // ---- fragment fetch for k16 slab s (0..7) of a stage --------------------
    auto LDFRAG = [&](uint32_t stage, int s,
                      uint32_t (&af)[2][4], uint32_t (&bf)[4][2]) {
        const uint32_t ab = stage + (s >> 2) * CHUNKB;
        const uint32_t bb = ab + 16384;
        const int kb = (s & 3) * 32;
        #pragma unroll
        for (int mt = 0; mt < 2; mt++) {
            int row = wm + mt * 16 + (lane & 15);
            uint32_t off = row * 128 + (lane >> 4) * 16 + kb;
            uint32_t ad = ab + (off ^ ((off >> 3) & 0x70));
            asm volatile(
                "ldmatrix.sync.aligned.m8n8.x4.shared.b16 {%0,%1,%2,%3}, [%4];"
                : "=r"(af[mt][0]), "=r"(af[mt][1]),
                  "=r"(af[mt][2]), "=r"(af[mt][3])
                : "r"(ad));
        }
        #pragma unroll
        for (int ntp = 0; ntp < 2; ntp++) {
            int row = wn + ntp * 16 + ((lane >> 4) & 1) * 8 + (lane & 7);
            uint32_t off = row * 128 + ((lane >> 3) & 1) * 16 + kb;
            uint32_t bd = bb + (off ^ ((off >> 3) & 0x70));
            asm volatile(
                "ldmatrix.sync.aligned.m8n8.x4.shared.b16 {%0,%1,%2,%3}, [%4];"
                : "=r"(bf[2 * ntp][0]), "=r"(bf[2 * ntp][1]),
                  "=r"(bf[2 * ntp + 1][0]), "=r"(bf[2 * ntp + 1][1])
                : "r"(bd));
        }
    };

    // ---- consumer: 8 k16 slabs of pair p, rotated, frag double-buffer -------
    auto COMP = [&](int p) {
        const uint32_t stage = base0 + (p % 3) * STAGEB;
        uint32_t af[2][2][4], bf[2][4][2];
        LDFRAG(stage, rot, af[0], bf[0]);
        #pragma unroll
        for (int sl = 0; sl < 8; sl++) {
            const int cur = sl & 1;
            if (sl < 7) LDFRAG(stage, (rot + sl + 1) & 7, af[cur ^ 1], bf[cur ^ 1]);
            #pragma unroll
            for (int mt = 0; mt < 2; mt++)
                #pragma unroll
                for (int nt = 0; nt < 4; nt++)
                    asm volatile(
                        "mma.sync.aligned.m16n8k16.row.col.f32.f16.f16.f32 "
                        "{%0,%1,%2,%3}, {%4,%5,%6,%7}, {%8,%9}, {%0,%1,%2,%3};\n"
                        : "+f"(acc[mt][nt][0]), "+f"(acc[mt][nt][1]),
                          "+f"(acc[mt][nt][2]), "+f"(acc[mt][nt][3])
                        : "r"(af[cur][mt][0]), "r"(af[cur][mt][1]),
                          "r"(af[cur][mt][2]), "r"(af[cur][mt][3]),
                          "r"(bf[cur][nt][0]), "r"(bf[cur][nt][1]));
        }
    };

    // ---- initial prefetch for phase (s=0, layer=0) --------------------------
    PREF(&g_hd[0][z][0][0], &g_Wp[z][0][0]);

    for (int s = 0; s < NSTEPS; s++) {
        #pragma unroll 1
        for (int layer = 0; layer < 2; layer++) {
            const int lz   = layer * 2 + z;
            const int hsel = s & 1;
            const __half* inp = layer ? &g_x1[0][0] : &g_y[0][0];
            const __half* W   = &g_Wp[lz][0][0];

            #pragma unroll
            for (int a = 0; a < 2; a++)
                #pragma unroll
                for (int b = 0; b < 4; b++)
                    #pragma unroll
                    for (int c = 0; c < 4; c++) acc[a][b][c] = 0.f;

            // G1: A of pair 0 (y-part; barrier-dependent)
            LOAD_A(0, inp, 512, 0); LOAD_A(1, inp, 512, 64);
            asm volatile("cp.async.commit_group;" ::: "memory");

            // consumption order {4,5,0,1,2,3}; loads issued before COMP
            // i=0: consume pair4 (G_pre)
            asm volatile("cp.async.wait_group 1;" ::: "memory");
            __syncthreads();
            COMP(4);
            // i=1: consume pair5 (G_pre); load pair1 (stage1 freed at sync)
            asm volatile("cp.async.wait_group 1;" ::: "memory");
            __syncthreads();
            LOAD_A(2, inp, 512, 128); LOAD_A(3, inp, 512, 192);
            LOAD_B(2, W); LOAD_B(3, W);
            asm volatile("cp.async.commit_group;" ::: "memory");
            COMP(5);
            // i=2: consume pair0 (G1); load pair2
            asm volatile("cp.async.wait_group 1;" ::: "memory");
            __syncthreads();
            LOAD_A(4, inp, 512, 256); LOAD_A(5, inp, 512, 320);
            LOAD_B(4, W); LOAD_B(5, W);
            asm volatile("cp.async.commit_group;" ::: "memory");
            COMP(0);
            // i=3: consume pair1 (G2); load pair3
            asm volatile("cp.async.wait_group 1;" ::: "memory");
            __syncthreads();
            LOAD_A(6, inp, 512, 384); LOAD_A(7, inp, 512, 448);
            LOAD_B(6, W); LOAD_B(7, W);
            asm volatile("cp.async.commit_group;" ::: "memory");
            COMP(1);
            // i=4: consume pair2 (G3)
            asm volatile("cp.async.wait_group 1;" ::: "memory");
            __syncthreads();
            COMP(2);
            // i=5: consume pair3 (G4)
            asm volatile("cp.async.wait_group 0;" ::: "memory");
            __syncthreads();
            COMP(3);
            __syncthreads();   // all COMP done before stage smem is reused

            // ---- epilogue: acc -> padded smem, fused cell update ------------
            char* gptr = smem + (base0 - sb);
            #pragma unroll
            for (int mt = 0; mt < 2; mt++)
                #pragma unroll
                for (int nt = 0; nt < 4; nt++) {
                    int r = wm + mt * 16 + (lane >> 2);
                    int c = wn + nt * 8 + (lane & 3) * 2;
                    *(float2*)(gptr + (size_t)((r * GSTRIDE + c) * 4)) =
                        make_float2(acc[mt][nt][0], acc[mt][nt][1]);
                    *(float2*)(gptr + (size_t)(((r + 8) * GSTRIDE + c) * 4)) =
                        make_float2(acc[mt][nt][2], acc[mt][nt][3]);
                }
            __syncthreads();

            #pragma unroll
            for (int it = 0; it < 8; it++) {
                int idx = tid + it * NTHREADS;      // 0..4095
                int bl  = idx >> 5;
                int jl  = idx & 31;
                float4 g4 = *(const float4*)(gptr + (size_t)((bl * GSTRIDE + jl * 4) * 4));
                float4 bs = *(const float4*)&g_bias[lz][(j0 + jl) * 4];
                int gb = row0 + bl;
                int j  = j0 + jl;
                float cc = sigf(g4.y + bs.y) * g_c[lz][gb][j]
                         + sigf(g4.x + bs.x) * tanhfast(g4.z + bs.z);
                float h  = sigf(g4.w + bs.w) * tanhfast(cc);
                g_c[lz][gb][j] = cc;
                __half hh = __float2half(h);
                g_hd[hsel ^ 1][lz][gb][j] = hh;
                if (layer == 0) {
                    g_x1[gb][z * 256 + j] = hh;
                } else {
                    g_y[gb][z * 256 + j] = hh;
                    out[(size_t)gb * (NSTEPS * 512) + (size_t)s * 512 + z * 256 + j] = h;
                }
            }
            __syncthreads();   // epilogue smem reads done before prefetch reuses it

            // ---- prefetch next phase (B + h-part A) over the barrier --------
            const bool last = (s == NSTEPS - 1) && (layer == 1);
            if (!last) {
                const __half* hN;
                const __half* WN;
                if (layer == 0) {                    // next: (s, 1)
                    hN = &g_hd[hsel][2 + z][0][0];
                    WN = &g_Wp[2 + z][0][0];
                } else {                             // next: (s+1, 0)
                    hN = &g_hd[hsel ^ 1][z][0][0];
                    WN = &g_Wp[z][0][0];
                }
                PREF(hN, WN);

                phase++;
                if (tid == 0) {
                    unsigned tgt = (unsigned)phase * 16u;
                    unsigned tmp;
                    asm volatile("atom.release.gpu.global.add.u32 %0, [%1], 1;"
                                 : "=r"(tmp) : "l"(barptr) : "memory");
                    unsigned v;
                    do {
                        asm volatile("ld.acquire.gpu.global.u32 %0, [%1];"
                                     : "=r"(v) : "l"(barptr) : "memory");
                    } while (v < tgt);
                }
                __syncthreads();
            }
        }
    }
}

// ---------------- weight/bias packing (runs once per launch) ----------------
__global__ void pack_weights(const float* __restrict__ Wih0, const float* __restrict__ Whh0,
                             const float* __restrict__ bih0, const float* __restrict__ bhh0,
                             const float* __restrict__ Wih1, const float* __restrict__ Whh1,
                             const float* __restrict__ bih1, const float* __restrict__ bhh1)
{
    long idx = (long)blockIdx.x * 256 + threadIdx.x;   // 0 .. 4*1024*768-1
    int lz  = (int)(idx / (1024 * 768));
    int rem = (int)(idx % (1024 * 768));
    int r = rem / 768;
    int k = rem % 768;
    int layer = lz >> 1, z = lz & 1;
    int gate = r & 3, j = r >> 2;
    int n = gate * 256 + j;
    const float* Wih = layer ? Wih1 : Wih0;
    const float* Whh = layer ? Whh1 : Whh0;
    float v = (k < 512) ? Wih[((size_t)z * 1024 + n) * 512 + k]
                        : Whh[((size_t)z * 1024 + n) * 256 + (k - 512)];
    g_Wp[lz][r][k] = __float2half(v);

    if (idx < 4096) {
        int blz = (int)(idx >> 10);
        int br  = (int)(idx & 1023);
        int bl = blz >> 1, bz = blz & 1;
        int bg = br & 3, bj = br >> 2;
        const float* bih = bl ? bih1 : bih0;
        const float* bhh = bl ? bhh1 : bhh0;
        g_bias[blz][br] = bih[bz * 1024 + bg * 256 + bj] + bhh[bz * 1024 + bg * 256 + bj];
    }
}

// ---------------- init: code -> (h0, c0); zero feedback; reset barriers -----
__global__ void lstm_init(const float* __restrict__ code)
{
    int idx = blockIdx.x * blockDim.x + threadIdx.x;
    if (idx < BATCH * 2048) {
        int b = idx >> 11;
        int t = idx & 2047;
        float v = code[idx];
        int l = (t >> 8) & 3;
        int j = t & 255;
        if (t < 1024) g_hd[0][l][b][j] = __float2half(v);
        else          g_c[l][b][j] = v;
    } else {
        int r = idx - BATCH * 2048;
        if (r < BATCH * 512) (&g_y[0][0])[r] = __float2half(0.f);
    }
    if (idx < 8) g_bar[idx][0] = 0u;
}

// ---------------- launch ----------------------------------------------------
extern "C" void kernel_launch(void* const* d_in, const int* in_sizes, int n_in,
                              void* d_out, int out_size)
{
    const float* code = (const float*)d_in[0];
    // d_in[1] = x : unused by the reference computation
    const float* Wih0 = (const float*)d_in[2];
    const float* Whh0 = (const float*)d_in[3];
    const float* bih0 = (const float*)d_in[4];
    const float* bhh0 = (const float*)d_in[5];
    const float* Wih1 = (const float*)d_in[6];
    const float* Whh1 = (const float*)d_in[7];
    const float* bih1 = (const float*)d_in[8];
    const float* bhh1 = (const float*)d_in[9];
    float* out = (float*)d_out;

    const int smem_bytes = 3 * STAGEB + 1024;   // 197632
    cudaFuncSetAttribute(lstm_persist, cudaFuncAttributeMaxDynamicSharedMemorySize,
                         smem_bytes);

    pack_weights<<<4 * 1024 * 768 / 256, 256>>>(Wih0, Whh0, bih0, bhh0,
                                                Wih1, Whh1, bih1, bhh1);
    lstm_init<<<(BATCH * 2048 + BATCH * 512) / 256, 256>>>(code);

    lstm_persist<<<128, NTHREADS, smem_bytes>>>(out);
}

// round 17
// speedup vs baseline: 2.0747x; 1.0610x over previous
#include <cuda_runtime.h>
#include <cuda_fp16.h>
#include <math.h>
#include <stdint.h>

#define HID     256
#define NSTEPS  52
#define BATCH   1024

// ---------------- persistent state (device globals; no allocation) ----------
__device__ __align__(16) __half g_hd[2][4][BATCH][HID]; // double-buffered h (fp16)
__device__ float  g_c[4][BATCH][HID];                   // full fp32 cell state
__device__ __align__(16) __half g_y [BATCH][512];       // layer-0 input (prev y)
__device__ __align__(16) __half g_x1[BATCH][512];       // layer-1 input (concat h)
__device__ __align__(16) __half g_Wp[4][1024][768];     // packed fp16 weights
__device__ float  g_bias[4][1024];                      // bih+bhh, row order j*4+gate
__device__ unsigned g_bar[8][32];                       // per-band barrier counters

// ---------------- helpers ---------------------------------------------------
__device__ __forceinline__ uint32_t smem_u32(const void* p) {
    uint32_t a;
    asm("{ .reg .u64 t; cvta.to.shared.u64 t, %1; cvt.u32.u64 %0, t; }" : "=r"(a) : "l"(p));
    return a;
}
__device__ __forceinline__ float tanha(float x) {
    float r;
    asm("tanh.approx.f32 %0, %1;" : "=f"(r) : "f"(x));
    return r;
}
__device__ __forceinline__ float sigf(float x) { return 0.5f * tanha(0.5f * x) + 0.5f; }

#define NTHREADS 512
#define CHUNKB  32768          // one k-chunk slot: [A 16K][B 16K]
#define STAGEB  65536          // one stage: 2 chunks (one pair)
#define GSTRIDE 132            // epilogue gate smem row stride (floats), padded

// ---------------- persistent fused LSTM kernel ------------------------------
// 128 CTAs (<=148 SMs -> co-resident). CTA bx: band=bx>>4 (batch rows band*128),
// sub=bx&15: n0=(sub>>1)*128 (gate-row tile), z=sub&1 (direction).
// 16 warps, 4x4 layout, each warp a 32x32 output tile over full K. fp16 MMA k16.
// K=768 in 12 chunks of 64; pairs p = chunks {2p,2p+1} -> stage p%3.
// Pair consumption order {4,5,0,1,2,3}: pairs 4,5 (h-part A + B) and B of pair 0
// are prefetched OVER the inter-CTA barrier (h is 2 phases old -> safe).
__global__ void __launch_bounds__(NTHREADS, 1)
lstm_persist(float* __restrict__ out)
{
    extern __shared__ char smem[];
    const uint32_t sb    = smem_u32(smem);
    const uint32_t base0 = (sb + 1023u) & ~1023u;

    const int tid  = threadIdx.x;
    const int lane = tid & 31;
    const int warp = tid >> 5;
    const int wm   = (warp >> 2) * 32;      // warp row offset (batch)
    const int wn   = (warp & 3) * 32;       // warp col offset (gates)
    const int rot  = (warp & 3) * 2;        // slab start rotation (de-convoy)

    const int bx   = blockIdx.x;
    const int band = bx >> 4;
    const int sub  = bx & 15;
    const int n0   = (sub >> 1) * 128;
    const int j0   = (sub >> 1) * 32;
    const int z    = sub & 1;
    const int row0 = band * 128;

    unsigned* barptr = &g_bar[band][0];
    int phase = 0;

    float acc[2][4][4];   // 32x32 warp tile

    // ---- chunk loaders: chunk c -> stage (c>>1)%3, half c&1 -----------------
    auto LOAD_A = [&](int c, const __half* src, int width, int kbase) {
        const uint32_t ab = base0 + ((c >> 1) % 3) * STAGEB + (c & 1) * CHUNKB;
        #pragma unroll
        for (int i = 0; i < 2; i++) {
            int idx = tid + i * NTHREADS;        // 0..1023
            int row = idx >> 3;
            int c8  = idx & 7;
            uint32_t off = row * 128 + c8 * 16;
            uint32_t sw  = off ^ ((off >> 3) & 0x70);
            const __half* s = src + (size_t)(row0 + row) * width + kbase + c8 * 8;
            asm volatile("cp.async.cg.shared.global [%0], [%1], 16;"
                         :: "r"(ab + sw), "l"(s));
        }
    };
    auto LOAD_B = [&](int c, const __half* Wsrc) {
        const uint32_t bb = base0 + ((c >> 1) % 3) * STAGEB + (c & 1) * CHUNKB + 16384;
        #pragma unroll
        for (int i = 0; i < 2; i++) {
            int idx = tid + i * NTHREADS;
            int row = idx >> 3;
            int c8  = idx & 7;
            uint32_t off = row * 128 + c8 * 16;
            uint32_t sw  = off ^ ((off >> 3) & 0x70);
            const __half* s = Wsrc + (size_t)(n0 + row) * 768 + c * 64 + c8 * 8;
            asm volatile("cp.async.cg.shared.global [%0], [%1], 16;"
                         :: "r"(bb + sw), "l"(s));
        }
    };

    // ---- prefetch group for a phase: B(0,1) + A+B(8..11); one commit --------
    auto PREF = [&](const __half* h_, const __half* W_) {
        LOAD_B(0, W_); LOAD_B(1, W_);
        #pragma unroll
        for (int c = 8; c < 12; c++) {
            LOAD_A(c, h_, 256, c * 64 - 512);
            LOAD_B(c, W_);
        }
        asm volatile("cp.async.commit_group;" ::: "memory");
    };

    // ---- fragment fetch for k16 slab s (0..7) of a stage --------------------
    auto LDFRAG = [&](uint32_t stage, int s,
                      uint32_t (&af)[2][4], uint32_t (&bf)[4][2]) {
        const uint32_t ab = stage + (s >> 2) * CHUNKB;
        const uint32_t bb = ab + 16384;
        const int kb = (s & 3) * 32;
        #pragma unroll
        for (int mt = 0; mt < 2; mt++) {
            int row = wm + mt * 16 + (lane & 15);
            uint32_t off = row * 128 + (lane >> 4) * 16 + kb;
            uint32_t ad = ab + (off ^ ((off >> 3) & 0x70));
            asm volatile(
                "ldmatrix.sync.aligned.m8n8.x4.shared.b16 {%0,%1,%2,%3}, [%4];"
                : "=r"(af[mt][0]), "=r"(af[mt][1]),
                  "=r"(af[mt][2]), "=r"(af[mt][3])
                : "r"(ad));
        }
        #pragma unroll
        for (int ntp = 0; ntp < 2; ntp++) {
            int row = wn + ntp * 16 + ((lane >> 4) & 1) * 8 + (lane & 7);
            uint32_t off = row * 128 + ((lane >> 3) & 1) * 16 + kb;
            uint32_t bd = bb + (off ^ ((off >> 3) & 0x70));
            asm volatile(
                "ldmatrix.sync.aligned.m8n8.x4.shared.b16 {%0,%1,%2,%3}, [%4];"
                : "=r"(bf[2 * ntp][0]), "=r"(bf[2 * ntp][1]),
                  "=r"(bf[2 * ntp + 1][0]), "=r"(bf[2 * ntp + 1][1])
                : "r"(bd));
        }
    };

    // ---- consumer: 8 k16 slabs of pair p, rotated, frag double-buffer -------
    auto COMP = [&](int p) {
        const uint32_t stage = base0 + (p % 3) * STAGEB;
        uint32_t af[2][2][4], bf[2][4][2];
        LDFRAG(stage, rot, af[0], bf[0]);
        #pragma unroll
        for (int sl = 0; sl < 8; sl++) {
            const int cur = sl & 1;
            if (sl < 7) LDFRAG(stage, (rot + sl + 1) & 7, af[cur ^ 1], bf[cur ^ 1]);
            #pragma unroll
            for (int mt = 0; mt < 2; mt++)
                #pragma unroll
                for (int nt = 0; nt < 4; nt++)
                    asm volatile(
                        "mma.sync.aligned.m16n8k16.row.col.f32.f16.f16.f32 "
                        "{%0,%1,%2,%3}, {%4,%5,%6,%7}, {%8,%9}, {%0,%1,%2,%3};\n"
                        : "+f"(acc[mt][nt][0]), "+f"(acc[mt][nt][1]),
                          "+f"(acc[mt][nt][2]), "+f"(acc[mt][nt][3])
                        : "r"(af[cur][mt][0]), "r"(af[cur][mt][1]),
                          "r"(af[cur][mt][2]), "r"(af[cur][mt][3]),
                          "r"(bf[cur][nt][0]), "r"(bf[cur][nt][1]));
        }
    };

    // ---- initial prefetch for phase (s=0, layer=0) --------------------------
    PREF(&g_hd[0][z][0][0], &g_Wp[z][0][0]);

    for (int s = 0; s < NSTEPS; s++) {
        #pragma unroll 1
        for (int layer = 0; layer < 2; layer++) {
            const int lz   = layer * 2 + z;
            const int hsel = s & 1;
            const __half* inp = layer ? &g_x1[0][0] : &g_y[0][0];
            const __half* W   = &g_Wp[lz][0][0];

            #pragma unroll
            for (int a = 0; a < 2; a++)
                #pragma unroll
                for (int b = 0; b < 4; b++)
                    #pragma unroll
                    for (int c = 0; c < 4; c++) acc[a][b][c] = 0.f;

            // G1: A of pair 0 (y-part; barrier-dependent)
            LOAD_A(0, inp, 512, 0); LOAD_A(1, inp, 512, 64);
            asm volatile("cp.async.commit_group;" ::: "memory");

            // consumption order {4,5,0,1,2,3}; loads issued before COMP
            asm volatile("cp.async.wait_group 1;" ::: "memory");
            __syncthreads();
            COMP(4);
            asm volatile("cp.async.wait_group 1;" ::: "memory");
            __syncthreads();
            LOAD_A(2, inp, 512, 128); LOAD_A(3, inp, 512, 192);
            LOAD_B(2, W); LOAD_B(3, W);
            asm volatile("cp.async.commit_group;" ::: "memory");
            COMP(5);
            asm volatile("cp.async.wait_group 1;" ::: "memory");
            __syncthreads();
            LOAD_A(4, inp, 512, 256); LOAD_A(5, inp, 512, 320);
            LOAD_B(4, W); LOAD_B(5, W);
            asm volatile("cp.async.commit_group;" ::: "memory");
            COMP(0);
            asm volatile("cp.async.wait_group 1;" ::: "memory");
            __syncthreads();
            LOAD_A(6, inp, 512, 384); LOAD_A(7, inp, 512, 448);
            LOAD_B(6, W); LOAD_B(7, W);
            asm volatile("cp.async.commit_group;" ::: "memory");
            COMP(1);
            asm volatile("cp.async.wait_group 1;" ::: "memory");
            __syncthreads();
            COMP(2);
            asm volatile("cp.async.wait_group 0;" ::: "memory");
            __syncthreads();
            COMP(3);

            // ---- epilogue: gate buffer lives in STAGE 1 (base0+STAGEB).
            // Safe without a pre-sync: COMP(3) reads only stage 0, and all
            // warps finished stage-1/2 reads before the i=5 sync above.
            // (The 2KB GSTRIDE padding overflow into stage 2 is likewise safe:
            // stage 2's last reader, COMP(2), completed before the i=5 sync.)
            char* gptr = smem + (base0 - sb) + STAGEB;
            #pragma unroll
            for (int mt = 0; mt < 2; mt++)
                #pragma unroll
                for (int nt = 0; nt < 4; nt++) {
                    int r = wm + mt * 16 + (lane >> 2);
                    int c = wn + nt * 8 + (lane & 3) * 2;
                    *(float2*)(gptr + (size_t)((r * GSTRIDE + c) * 4)) =
                        make_float2(acc[mt][nt][0], acc[mt][nt][1]);
                    *(float2*)(gptr + (size_t)(((r + 8) * GSTRIDE + c) * 4)) =
                        make_float2(acc[mt][nt][2], acc[mt][nt][3]);
                }
            __syncthreads();

            #pragma unroll
            for (int it = 0; it < 8; it++) {
                int idx = tid + it * NTHREADS;      // 0..4095
                int bl  = idx >> 5;
                int jl  = idx & 31;
                float4 g4 = *(const float4*)(gptr + (size_t)((bl * GSTRIDE + jl * 4) * 4));
                float4 bs = *(const float4*)&g_bias[lz][(j0 + jl) * 4];
                int gb = row0 + bl;
                int j  = j0 + jl;
                float cc = sigf(g4.y + bs.y) * g_c[lz][gb][j]
                         + sigf(g4.x + bs.x) * tanha(g4.z + bs.z);
                float h  = sigf(g4.w + bs.w) * tanha(cc);
                g_c[lz][gb][j] = cc;
                __half hh = __float2half(h);
                g_hd[hsel ^ 1][lz][gb][j] = hh;
                if (layer == 0) {
                    g_x1[gb][z * 256 + j] = hh;
                } else {
                    g_y[gb][z * 256 + j] = hh;
                    out[(size_t)gb * (NSTEPS * 512) + (size_t)s * 512 + z * 256 + j] = h;
                }
            }
            __syncthreads();   // epilogue smem reads done before prefetch reuses it

            // ---- prefetch next phase (B + h-part A) over the barrier --------
            const bool last = (s == NSTEPS - 1) && (layer == 1);
            if (!last) {
                const __half* hN;
                const __half* WN;
                if (layer == 0) {                    // next: (s, 1)
                    hN = &g_hd[hsel][2 + z][0][0];
                    WN = &g_Wp[2 + z][0][0];
                } else {                             // next: (s+1, 0)
                    hN = &g_hd[hsel ^ 1][z][0][0];
                    WN = &g_Wp[z][0][0];
                }
                PREF(hN, WN);

                phase++;
                if (tid == 0) {
                    unsigned tgt = (unsigned)phase * 16u;
                    unsigned tmp;
                    asm volatile("atom.release.gpu.global.add.u32 %0, [%1], 1;"
                                 : "=r"(tmp) : "l"(barptr) : "memory");
                    unsigned v;
                    do {
                        asm volatile("ld.acquire.gpu.global.u32 %0, [%1];"
                                     : "=r"(v) : "l"(barptr) : "memory");
                    } while (v < tgt);
                }
                __syncthreads();
            }
        }
    }
}

// ---------------- weight/bias packing (runs once per launch) ----------------
__global__ void pack_weights(const float* __restrict__ Wih0, const float* __restrict__ Whh0,
                             const float* __restrict__ bih0, const float* __restrict__ bhh0,
                             const float* __restrict__ Wih1, const float* __restrict__ Whh1,
                             const float* __restrict__ bih1, const float* __restrict__ bhh1)
{
    long idx = (long)blockIdx.x * 256 + threadIdx.x;   // 0 .. 4*1024*768-1
    int lz  = (int)(idx / (1024 * 768));
    int rem = (int)(idx % (1024 * 768));
    int r = rem / 768;
    int k = rem % 768;
    int layer = lz >> 1, z = lz & 1;
    int gate = r & 3, j = r >> 2;
    int n = gate * 256 + j;
    const float* Wih = layer ? Wih1 : Wih0;
    const float* Whh = layer ? Whh1 : Whh0;
    float v = (k < 512) ? Wih[((size_t)z * 1024 + n) * 512 + k]
                        : Whh[((size_t)z * 1024 + n) * 256 + (k - 512)];
    g_Wp[lz][r][k] = __float2half(v);

    if (idx < 4096) {
        int blz = (int)(idx >> 10);
        int br  = (int)(idx & 1023);
        int bl = blz >> 1, bz = blz & 1;
        int bg = br & 3, bj = br >> 2;
        const float* bih = bl ? bih1 : bih0;
        const float* bhh = bl ? bhh1 : bhh0;
        g_bias[blz][br] = bih[bz * 1024 + bg * 256 + bj] + bhh[bz * 1024 + bg * 256 + bj];
    }
}

// ---------------- init: code -> (h0, c0); zero feedback; reset barriers -----
__global__ void lstm_init(const float* __restrict__ code)
{
    int idx = blockIdx.x * blockDim.x + threadIdx.x;
    if (idx < BATCH * 2048) {
        int b = idx >> 11;
        int t = idx & 2047;
        float v = code[idx];
        int l = (t >> 8) & 3;
        int j = t & 255;
        if (t < 1024) g_hd[0][l][b][j] = __float2half(v);
        else          g_c[l][b][j] = v;
    } else {
        int r = idx - BATCH * 2048;
        if (r < BATCH * 512) (&g_y[0][0])[r] = __float2half(0.f);
    }
    if (idx < 8) g_bar[idx][0] = 0u;
}

// ---------------- launch ----------------------------------------------------
extern "C" void kernel_launch(void* const* d_in, const int* in_sizes, int n_in,
                              void* d_out, int out_size)
{
    const float* code = (const float*)d_in[0];
    // d_in[1] = x : unused by the reference computation
    const float* Wih0 = (const float*)d_in[2];
    const float* Whh0 = (const float*)d_in[3];
    const float* bih0 = (const float*)d_in[4];
    const float* bhh0 = (const float*)d_in[5];
    const float* Wih1 = (const float*)d_in[6];
    const float* Whh1 = (const float*)d_in[7];
    const float* bih1 = (const float*)d_in[8];
    const float* bhh1 = (const float*)d_in[9];
    float* out = (float*)d_out;

    const int smem_bytes = 3 * STAGEB + 1024;   // 197632
    cudaFuncSetAttribute(lstm_persist, cudaFuncAttributeMaxDynamicSharedMemorySize,
                         smem_bytes);

    pack_weights<<<4 * 1024 * 768 / 256, 256>>>(Wih0, Whh0, bih0, bhh0,
                                                Wih1, Whh1, bih1, bhh1);
    lstm_init<<<(BATCH * 2048 + BATCH * 512) / 256, 256>>>(code);

    lstm_persist<<<128, NTHREADS, smem_bytes>>>(out);
}